// round 9
// baseline (speedup 1.0000x reference)
#include <cuda_runtime.h>
#include <cuda_fp16.h>
#include <math.h>
#include <stdint.h>

#define NB 8
#define SL 8192
#define ED 512
#define NH 8
#define DH 64
#define MT (NB*SL)

// ---------------- scratch (device globals; no allocation) -------------------
__device__ float g_kv[NB * NH * DH * DH];
__device__ float g_ksum[NB * NH * DH];
// input splits
__device__ __half g_xqh[(size_t)MT * ED];
__device__ __half g_xql[(size_t)MT * ED];
__device__ __half g_xkh[(size_t)MT * ED];
__device__ __half g_xkl[(size_t)MT * ED];
__device__ __half g_xvh[(size_t)MT * ED];
__device__ __half g_xvl[(size_t)MT * ED];
// Q projection (feature-mapped) fp16 hi/lo, [n,s,e]
__device__ __half g_qh[(size_t)MT * ED];
__device__ __half g_ql[(size_t)MT * ED];
// K/V projections TRANSPOSED per head: [n,h,d(64),s(8192)], fp16 hi/lo
__device__ __half g_kth[(size_t)MT * ED];
__device__ __half g_ktl[(size_t)MT * ED];
__device__ __half g_vth[(size_t)MT * ED];
__device__ __half g_vtl[(size_t)MT * ED];
// attn output splits
__device__ __half g_aoh[(size_t)MT * ED];
__device__ __half g_aol[(size_t)MT * ED];
// fp16 weights
__device__ __half g_w16[4][ED * ED];
// augmented KV blob (80 rows x 64 cols, swizzled)
__device__ __half g_kvah[NB * NH * 80 * 64];
__device__ __half g_kval[NB * NH * 80 * 64];

// ---------------- helpers ---------------------------------------------------
__device__ __forceinline__ uint32_t smem_u32(const void* p) {
    uint32_t a;
    asm("{ .reg .u64 t; cvta.to.shared.u64 t, %1; cvt.u32.u64 %0, t; }" : "=r"(a) : "l"(p));
    return a;
}
__device__ __forceinline__ uint32_t pack2h(__half a, __half b) {
    __half2 t(a, b);
    return *reinterpret_cast<uint32_t*>(&t);
}
__device__ __forceinline__ void cp16(uint32_t s, const void* g) {
    asm volatile("cp.async.cg.shared.global [%0], [%1], 16;" :: "r"(s), "l"(g));
}
#define CP_COMMIT() asm volatile("cp.async.commit_group;" ::: "memory")
#define CP_WAIT(N)  asm volatile("cp.async.wait_group %0;" :: "n"(N) : "memory")

#define LDSM4(r, addr)                                                         \
    asm volatile("ldmatrix.sync.aligned.m8n8.x4.shared.b16 {%0,%1,%2,%3}, [%4];" \
        : "=r"((r)[0]), "=r"((r)[1]), "=r"((r)[2]), "=r"((r)[3]) : "r"(addr))

#define MMA16816(d, a, b0, b1)                                                 \
    asm volatile("mma.sync.aligned.m16n8k16.row.col.f32.f16.f16.f32 "          \
        "{%0,%1,%2,%3}, {%4,%5,%6,%7}, {%8,%9}, {%0,%1,%2,%3};"                \
        : "+f"((d)[0]), "+f"((d)[1]), "+f"((d)[2]), "+f"((d)[3])               \
        : "r"((a)[0]), "r"((a)[1]), "r"((a)[2]), "r"((a)[3]), "r"(b0), "r"(b1))

// ---------------- split fp32 -> fp16 hi/lo -----------------------------------
__global__ __launch_bounds__(256) void split_kernel(const float* __restrict__ src,
                                                    __half* __restrict__ hi,
                                                    __half* __restrict__ lo, int n4)
{
    int i = blockIdx.x * blockDim.x + threadIdx.x;
    if (i >= n4) return;
    float4 v = ((const float4*)src)[i];
    __half h0 = __float2half_rn(v.x), h1 = __float2half_rn(v.y);
    __half h2 = __float2half_rn(v.z), h3 = __float2half_rn(v.w);
    __half l0 = __float2half_rn(v.x - __half2float(h0));
    __half l1 = __float2half_rn(v.y - __half2float(h1));
    __half l2 = __float2half_rn(v.z - __half2float(h2));
    __half l3 = __float2half_rn(v.w - __half2float(h3));
    uint2 hp, lp;
    hp.x = pack2h(h0, h1); hp.y = pack2h(h2, h3);
    lp.x = pack2h(l0, l1); lp.y = pack2h(l2, l3);
    ((uint2*)hi)[i] = hp;
    ((uint2*)lo)[i] = lp;
}

__global__ __launch_bounds__(256) void wconv_kernel(const float* __restrict__ src,
                                                    __half* __restrict__ dst, int n4)
{
    int i = blockIdx.x * blockDim.x + threadIdx.x;
    if (i >= n4) return;
    float4 v = ((const float4*)src)[i];
    uint2 p;
    p.x = pack2h(__float2half_rn(v.x), __float2half_rn(v.y));
    p.y = pack2h(__float2half_rn(v.z), __float2half_rn(v.w));
    ((uint2*)dst)[i] = p;
}

// ---------------- fp16 2-term GEMM (proven R5 config) ------------------------
// OMODE: 0 = fp32 C, 1 = fp16 hi/lo [n,s,e], 2 = fp16 hi/lo transposed [n,h,d,s]
#define AH_OFF   0
#define AL_OFF   16384
#define B_OFF    32768
#define STAGE_SZ 65536
#define GSMEM    (2 * STAGE_SZ)

__device__ __forceinline__ void issue_loads(uint32_t st,
                                            const __half* __restrict__ Ah,
                                            const __half* __restrict__ Al,
                                            const __half* __restrict__ Bh,
                                            int bm, int bn, int ch, int tid)
{
    const int kc = ch * 64;
#pragma unroll
    for (int i = 0; i < 2; i++) {
        const int idx = tid + i * 512;
        const int row = idx >> 3;
        const int c = idx & 7;
        const uint32_t soff = row * 128 + ((c ^ (row & 7)) << 4);
        const size_t goff = (size_t)(bm + row) * ED + kc + c * 8;
        cp16(st + AH_OFF + soff, Ah + goff);
        cp16(st + AL_OFF + soff, Al + goff);
    }
#pragma unroll
    for (int i = 0; i < 4; i++) {
        const int idx = tid + i * 512;
        const int row = idx >> 3;
        const int c = idx & 7;
        cp16(st + B_OFF + row * 128 + ((c ^ (row & 7)) << 4),
             Bh + (size_t)(bn + row) * ED + kc + c * 8);
    }
    CP_COMMIT();
}

template <int FEAT, int OMODE>
__global__ __launch_bounds__(512, 1) void gemm_mma(const __half* __restrict__ Ah,
                                                   const __half* __restrict__ Al,
                                                   const __half* __restrict__ Bh,
                                                   const float* __restrict__ bias,
                                                   float* __restrict__ C,
                                                   __half* __restrict__ Ch,
                                                   __half* __restrict__ Cl)
{
    extern __shared__ char smem_raw[];
    const uint32_t sb = smem_u32(smem_raw);

    const int tid = threadIdx.x;
    const int lane = tid & 31;
    const int wid = tid >> 5;
    const int wm = wid >> 2;
    const int wn = wid & 3;
    const int bm = blockIdx.y * 128;
    const int bn = blockIdx.x * 256;

    float acc[2][8][4];
#pragma unroll
    for (int i = 0; i < 2; i++)
#pragma unroll
        for (int j = 0; j < 8; j++)
#pragma unroll
            for (int q = 0; q < 4; q++) acc[i][j][q] = 0.f;

    issue_loads(sb, Ah, Al, Bh, bm, bn, 0, tid);

#pragma unroll 1
    for (int ch = 0; ch < 8; ch++) {
        const uint32_t cur = sb + (ch & 1) * STAGE_SZ;

        if (ch < 7) {
            issue_loads(sb + ((ch + 1) & 1) * STAGE_SZ, Ah, Al, Bh, bm, bn, ch + 1, tid);
            CP_WAIT(1);
        } else {
            CP_WAIT(0);
        }
        __syncthreads();

        const uint32_t sAh = cur + AH_OFF;
        const uint32_t sAl = cur + AL_OFF;
        const uint32_t sB  = cur + B_OFF;

        uint32_t fa[2][2][2][4];
        uint32_t fb[2][4];

        #define LOAD_A(s16, buf)                                               \
        {                                                                      \
            _Pragma("unroll")                                                  \
            for (int mf = 0; mf < 2; mf++) {                                   \
                const int arow = wm * 32 + mf * 16 + (lane & 15);              \
                const int achk = (s16) * 2 + (lane >> 4);                      \
                const uint32_t aoff = arow * 128 + ((achk ^ (arow & 7)) << 4); \
                LDSM4(fa[buf][mf][0], sAh + aoff);                             \
                LDSM4(fa[buf][mf][1], sAl + aoff);                             \
            }                                                                  \
        }
        #define LOAD_B(s16, nf, buf)                                           \
        {                                                                       \
            const int brow = wn * 64 + (nf) * 16 + (lane & 7) + ((lane >> 4) << 3); \
            const int bchk = (s16) * 2 + ((lane >> 3) & 1);                    \
            LDSM4(fb[buf], sB + brow * 128 + ((bchk ^ (brow & 7)) << 4));      \
        }

        LOAD_A(0, 0);
        LOAD_B(0, 0, 0);

#pragma unroll
        for (int s16 = 0; s16 < 4; s16++) {
            const int ab = s16 & 1;
#pragma unroll
            for (int nf = 0; nf < 4; nf++) {
                const int bb = nf & 1;
                if (nf < 3) {
                    LOAD_B(s16, nf + 1, bb ^ 1);
                } else if (s16 < 3) {
                    LOAD_A(s16 + 1, ab ^ 1);
                    LOAD_B(s16 + 1, 0, bb ^ 1);
                }
#pragma unroll
                for (int mf = 0; mf < 2; mf++) {
                    MMA16816(acc[mf][2 * nf],     fa[ab][mf][0], fb[bb][0], fb[bb][1]);
                    MMA16816(acc[mf][2 * nf + 1], fa[ab][mf][0], fb[bb][2], fb[bb][3]);
                }
#pragma unroll
                for (int mf = 0; mf < 2; mf++) {
                    MMA16816(acc[mf][2 * nf],     fa[ab][mf][1], fb[bb][0], fb[bb][1]);
                    MMA16816(acc[mf][2 * nf + 1], fa[ab][mf][1], fb[bb][2], fb[bb][3]);
                }
            }
        }
        #undef LOAD_A
        #undef LOAD_B
        __syncthreads();
    }

    // Epilogue
#pragma unroll
    for (int mf = 0; mf < 2; mf++) {
        const int row0 = bm + wm * 32 + mf * 16 + (lane >> 2);
#pragma unroll
        for (int nf8 = 0; nf8 < 8; nf8++) {
            const int col = bn + wn * 64 + nf8 * 8 + (lane & 3) * 2;
            const float b0 = bias[col], b1 = bias[col + 1];
            float x0 = acc[mf][nf8][0] + b0;
            float x1 = acc[mf][nf8][1] + b1;
            float x2 = acc[mf][nf8][2] + b0;
            float x3 = acc[mf][nf8][3] + b1;
            if (FEAT) {
                x0 = (x0 > 0.f) ? (x0 + 1.f) : expf(x0);
                x1 = (x1 > 0.f) ? (x1 + 1.f) : expf(x1);
                x2 = (x2 > 0.f) ? (x2 + 1.f) : expf(x2);
                x3 = (x3 > 0.f) ? (x3 + 1.f) : expf(x3);
            }
            if (OMODE == 0) {
                *(float2*)&C[(size_t)row0 * ED + col]       = make_float2(x0, x1);
                *(float2*)&C[(size_t)(row0 + 8) * ED + col] = make_float2(x2, x3);
            } else {
                __half h0 = __float2half_rn(x0), h1 = __float2half_rn(x1);
                __half h2 = __float2half_rn(x2), h3 = __float2half_rn(x3);
                __half e0 = __float2half_rn(x0 - __half2float(h0));
                __half e1 = __float2half_rn(x1 - __half2float(h1));
                __half e2 = __float2half_rn(x2 - __half2float(h2));
                __half e3 = __float2half_rn(x3 - __half2float(h3));
                if (OMODE == 1) {
                    *(uint32_t*)&Ch[(size_t)row0 * ED + col]       = pack2h(h0, h1);
                    *(uint32_t*)&Cl[(size_t)row0 * ED + col]       = pack2h(e0, e1);
                    *(uint32_t*)&Ch[(size_t)(row0 + 8) * ED + col] = pack2h(h2, h3);
                    *(uint32_t*)&Cl[(size_t)(row0 + 8) * ED + col] = pack2h(e2, e3);
                } else {
                    // transposed per head: [n, h, d, s]
                    const int n_ = row0 >> 13;
                    const int s_ = row0 & (SL - 1);
                    const int h_ = col >> 6;
                    const int d_ = col & 63;
                    const size_t base = ((size_t)(n_ * NH + h_) * DH + d_) * SL + s_;
                    Ch[base]          = h0;  Cl[base]          = e0;
                    Ch[base + SL]     = h1;  Cl[base + SL]     = e1;
                    Ch[base + 8]      = h2;  Cl[base + 8]      = e2;
                    Ch[base + SL + 8] = h3;  Cl[base + SL + 8] = e3;
                }
            }
        }
    }
}

// ---------------- zeroing ----------------------------------------------------
__global__ void zero_small()
{
    int i = blockIdx.x * blockDim.x + threadIdx.x;
    if (i < NB * NH * DH * DH) g_kv[i] = 0.f;
    if (i < NB * NH * DH)      g_ksum[i] = 0.f;
}

// ---------------- tensorized KV from transposed operands ---------------------
// KV[m,d] = sum_s Vt[m,s] * Kt[d,s]; Ksum[d] = sum_s Kt[d,s]. 3-term fp16.
#define KVS_VH 0
#define KVS_VL 8192
#define KVS_KH 16384
#define KVS_KL 24576
#define KVS_STAGE 32768
#define KVS_SMEM  65536

__device__ __forceinline__ void kv_issue(uint32_t sb, int stage, size_t tb,
                                         int s0, int tid)
{
#pragma unroll
    for (int it = 0; it < 8; it++) {
        const int idx = tid + it * 256;
        const int t = idx >> 9;
        const int r = (idx >> 3) & 63;
        const int c = idx & 7;
        const __half* src = (t == 0) ? g_vth : (t == 1) ? g_vtl
                          : (t == 2) ? g_kth : g_ktl;
        cp16(sb + stage * KVS_STAGE + t * 8192 + r * 128 + ((c ^ (r & 7)) << 4),
             src + tb + (size_t)r * SL + s0 + c * 8);
    }
    CP_COMMIT();
}

__global__ __launch_bounds__(256) void kv_kernel()
{
    extern __shared__ char smem_raw[];
    const uint32_t sb = smem_u32(smem_raw);
    const int tid = threadIdx.x;
    const int lane = tid & 31;
    const int wid = tid >> 5;
    const int wm = wid >> 1;        // 0..3 : 16 m-rows
    const int wn = wid & 1;         // 0..1 : 32 d-cols
    const int sp = blockIdx.x;      // 0..7 s-split
    const int h = blockIdx.y;
    const int n = blockIdx.z;
    const int nh = n * NH + h;
    const size_t tb = (size_t)nh * DH * SL;
    const int s_base = sp * (SL / 8);   // 1024 per split

    float acc[4][4];
#pragma unroll
    for (int j = 0; j < 4; j++)
#pragma unroll
        for (int q = 0; q < 4; q++) acc[j][q] = 0.f;
    float ks = 0.f;
    const int sum_d = tid & 63;
    const int sum_p = tid >> 6;

    kv_issue(sb, 0, tb, s_base, tid);

#pragma unroll 1
    for (int it = 0; it < 16; it++) {
        if (it < 15) { kv_issue(sb, (it + 1) & 1, tb, s_base + (it + 1) * 64, tid); CP_WAIT(1); }
        else CP_WAIT(0);
        __syncthreads();
        const uint32_t st = sb + (it & 1) * KVS_STAGE;
        char* stc = smem_raw + (it & 1) * KVS_STAGE;

#pragma unroll
        for (int kstep = 0; kstep < 4; kstep++) {
            uint32_t favh[4], favl[4];
            {
                const int arow = wm * 16 + (lane & 15);
                const int achk = kstep * 2 + (lane >> 4);
                const uint32_t aoff = arow * 128 + ((achk ^ (arow & 7)) << 4);
                LDSM4(favh, st + KVS_VH + aoff);
                LDSM4(favl, st + KVS_VL + aoff);
            }
            uint32_t fbh[2][4], fbl[2][4];
#pragma unroll
            for (int p = 0; p < 2; p++) {
                const int brow = wn * 32 + p * 16 + (lane & 7) + ((lane >> 4) << 3);
                const int bchk = kstep * 2 + ((lane >> 3) & 1);
                const uint32_t boff = brow * 128 + ((bchk ^ (brow & 7)) << 4);
                LDSM4(fbh[p], st + KVS_KH + boff);
                LDSM4(fbl[p], st + KVS_KL + boff);
            }
#pragma unroll
            for (int j = 0; j < 4; j++) {
                uint32_t b0h = fbh[j >> 1][(j & 1) * 2], b1h = fbh[j >> 1][(j & 1) * 2 + 1];
                uint32_t b0l = fbl[j >> 1][(j & 1) * 2], b1l = fbl[j >> 1][(j & 1) * 2 + 1];
                MMA16816(acc[j], favh, b0h, b1h);
                MMA16816(acc[j], favh, b0l, b1l);
                MMA16816(acc[j], favl, b0h, b1h);
            }
        }
        // Ksum: sum over s of Kt (hi+lo)
#pragma unroll
        for (int i = 0; i < 8; i++) {
            uint32_t off = sum_d * 128 + sum_p * 32 + i * 4;
            uint32_t sw = off ^ ((off >> 3) & 0x70);
            __half2 a = *(__half2*)(stc + KVS_KH + sw);
            __half2 b = *(__half2*)(stc + KVS_KL + sw);
            ks += __half2float(a.x) + __half2float(a.y)
                + __half2float(b.x) + __half2float(b.y);
        }
        __syncthreads();
    }

    const int g = lane >> 2, tig = lane & 3;
    float* kvout = g_kv + nh * 4096;
#pragma unroll
    for (int j = 0; j < 4; j++) {
        const int d = wn * 32 + j * 8 + tig * 2;
        const int m = wm * 16 + g;
        atomicAdd(&kvout[m * 64 + d],           acc[j][0]);
        atomicAdd(&kvout[m * 64 + d + 1],       acc[j][1]);
        atomicAdd(&kvout[(m + 8) * 64 + d],     acc[j][2]);
        atomicAdd(&kvout[(m + 8) * 64 + d + 1], acc[j][3]);
    }
    atomicAdd(&g_ksum[nh * 64 + sum_d], ks);
}

// ---------------- KV finalize: fp32 -> augmented fp16 hi/lo (swizzled) -------
__global__ __launch_bounds__(256) void kv_finalize()
{
    const int nh = blockIdx.x;
    const float* kv = g_kv + nh * 4096;
    const float* ks = g_ksum + nh * 64;
    char* oh = (char*)g_kvah + (size_t)nh * 10240;
    char* ol = (char*)g_kval + (size_t)nh * 10240;
    for (int idx = threadIdx.x; idx < 80 * 64; idx += 256) {
        const int r = idx >> 6, d = idx & 63;
        float x = (r < 64) ? kv[r * 64 + d] : (r == 64 ? ks[d] : 0.f);
        __half hh = __float2half_rn(x);
        __half ll = __float2half_rn(x - __half2float(hh));
        uint32_t off = r * 128 + d * 2;
        uint32_t sw = off ^ ((off >> 3) & 0x70);
        *(__half*)(oh + sw) = hh;
        *(__half*)(ol + sw) = ll;
    }
}

// ---------------- tensorized attn (proven R8) ---------------------------------
#define AT_QH 0
#define AT_QL 16384
#define AT_BH 32768
#define AT_BL 43008
#define AT_SMEM 53248

__global__ __launch_bounds__(256) void attn_kernel()
{
    extern __shared__ char smem_raw[];
    const uint32_t sb = smem_u32(smem_raw);
    const int tid = threadIdx.x;
    const int lane = tid & 31;
    const int wid = tid >> 5;
    const int l0 = blockIdx.x * 128;
    const int h = blockIdx.y;
    const int n = blockIdx.z;
    const int nh = n * NH + h;

#pragma unroll
    for (int it = 0; it < 8; it++) {
        int idx = tid + it * 256;
        int buf = idx >> 10;
        int r = (idx >> 3) & 127;
        int c = idx & 7;
        uint32_t soff = (buf ? AT_QL : AT_QH) + r * 128 + ((c ^ (r & 7)) << 4);
        const __half* src = buf ? g_ql : g_qh;
        cp16(sb + soff, src + (size_t)(n * SL + l0 + r) * ED + h * DH + c * 8);
    }
#pragma unroll
    for (int it = 0; it < 5; it++) {
        int idx = tid + it * 256;
        int buf = idx >= 640;
        int ch = buf ? idx - 640 : idx;
        cp16(sb + (buf ? AT_BL : AT_BH) + ch * 16,
             (buf ? g_kval : g_kvah) + (size_t)nh * 5120 + ch * 8);
    }
    CP_COMMIT();
    CP_WAIT(0);
    __syncthreads();

    float acc[9][4];
#pragma unroll
    for (int j = 0; j < 9; j++)
#pragma unroll
        for (int q = 0; q < 4; q++) acc[j][q] = 0.f;

#pragma unroll
    for (int kstep = 0; kstep < 4; kstep++) {
        uint32_t fah[4], fal[4];
        {
            const int arow = wid * 16 + (lane & 15);
            const int achk = kstep * 2 + (lane >> 4);
            const uint32_t aoff = arow * 128 + ((achk ^ (arow & 7)) << 4);
            LDSM4(fah, sb + AT_QH + aoff);
            LDSM4(fal, sb + AT_QL + aoff);
        }
        uint32_t fbh[5][4], fbl[5][4];
#pragma unroll
        for (int p = 0; p < 5; p++) {
            const int brow = p * 16 + (lane & 7) + ((lane >> 4) << 3);
            const int bchk = kstep * 2 + ((lane >> 3) & 1);
            const uint32_t boff = brow * 128 + ((bchk ^ (brow & 7)) << 4);
            LDSM4(fbh[p], sb + AT_BH + boff);
            LDSM4(fbl[p], sb + AT_BL + boff);
        }
#pragma unroll
        for (int j = 0; j < 9; j++) {
            uint32_t bh0 = fbh[j >> 1][(j & 1) * 2], bh1 = fbh[j >> 1][(j & 1) * 2 + 1];
            uint32_t bl0 = fbl[j >> 1][(j & 1) * 2], bl1 = fbl[j >> 1][(j & 1) * 2 + 1];
            MMA16816(acc[j], fah, bh0, bh1);
            MMA16816(acc[j], fah, bl0, bl1);
            MMA16816(acc[j], fal, bh0, bh1);
        }
    }

    const float zd0 = __shfl_sync(0xFFFFFFFFu, acc[8][0], lane & ~3);
    const float zd1 = __shfl_sync(0xFFFFFFFFu, acc[8][2], lane & ~3);
    const float z0 = 1.f / (fmaxf(zd0, 0.f) + 1e-6f);
    const float z1 = 1.f / (fmaxf(zd1, 0.f) + 1e-6f);
    const int g = lane >> 2, tig = lane & 3;
    const int row0 = l0 + wid * 16 + g;

#pragma unroll
    for (int j = 0; j < 8; j++) {
        const int e = h * DH + j * 8 + tig * 2;
        float x0 = acc[j][0] * z0, x1 = acc[j][1] * z0;
        float x2 = acc[j][2] * z1, x3 = acc[j][3] * z1;
        __half h0 = __float2half_rn(x0), h1 = __float2half_rn(x1);
        __half h2 = __float2half_rn(x2), h3 = __float2half_rn(x3);
        __half e0 = __float2half_rn(x0 - __half2float(h0));
        __half e1 = __float2half_rn(x1 - __half2float(h1));
        __half e2 = __float2half_rn(x2 - __half2float(h2));
        __half e3 = __float2half_rn(x3 - __half2float(h3));
        *(uint32_t*)&g_aoh[(size_t)(n * SL + row0) * ED + e]     = pack2h(h0, h1);
        *(uint32_t*)&g_aol[(size_t)(n * SL + row0) * ED + e]     = pack2h(e0, e1);
        *(uint32_t*)&g_aoh[(size_t)(n * SL + row0 + 8) * ED + e] = pack2h(h2, h3);
        *(uint32_t*)&g_aol[(size_t)(n * SL + row0 + 8) * ED + e] = pack2h(e2, e3);
    }
}

// ---------------- launch -----------------------------------------------------
extern "C" void kernel_launch(void* const* d_in, const int* in_sizes, int n_in,
                              void* d_out, int out_size)
{
    const float* q_in = (const float*)d_in[0];
    const float* k_in = (const float*)d_in[1];
    const float* v_in = (const float*)d_in[2];
    const float* Wq = (const float*)d_in[3];
    const float* bq = (const float*)d_in[4];
    const float* Wk = (const float*)d_in[5];
    const float* bk = (const float*)d_in[6];
    const float* Wv = (const float*)d_in[7];
    const float* bv = (const float*)d_in[8];
    const float* Wo = (const float*)d_in[9];
    const float* bo = (const float*)d_in[10];
    float* out = (float*)d_out;

    __half *xqh, *xql, *xkh, *xkl, *xvh, *xvl;
    __half *qh, *ql, *kth, *ktl, *vth, *vtl, *aoh, *aol, *w16;
    cudaGetSymbolAddress((void**)&xqh, g_xqh);
    cudaGetSymbolAddress((void**)&xql, g_xql);
    cudaGetSymbolAddress((void**)&xkh, g_xkh);
    cudaGetSymbolAddress((void**)&xkl, g_xkl);
    cudaGetSymbolAddress((void**)&xvh, g_xvh);
    cudaGetSymbolAddress((void**)&xvl, g_xvl);
    cudaGetSymbolAddress((void**)&qh, g_qh);
    cudaGetSymbolAddress((void**)&ql, g_ql);
    cudaGetSymbolAddress((void**)&kth, g_kth);
    cudaGetSymbolAddress((void**)&ktl, g_ktl);
    cudaGetSymbolAddress((void**)&vth, g_vth);
    cudaGetSymbolAddress((void**)&vtl, g_vtl);
    cudaGetSymbolAddress((void**)&aoh, g_aoh);
    cudaGetSymbolAddress((void**)&aol, g_aol);
    cudaGetSymbolAddress((void**)&w16, g_w16);
    __half* wq16 = w16;
    __half* wk16 = w16 + (size_t)ED * ED;
    __half* wv16 = w16 + (size_t)2 * ED * ED;
    __half* wo16 = w16 + (size_t)3 * ED * ED;

    static cudaStream_t s1, s2, s3;
    static cudaEvent_t ev0, evSK, evSV, evW;
    static bool inited = false;
    if (!inited) {
        cudaStreamCreateWithFlags(&s1, cudaStreamNonBlocking);
        cudaStreamCreateWithFlags(&s2, cudaStreamNonBlocking);
        cudaStreamCreateWithFlags(&s3, cudaStreamNonBlocking);
        cudaEventCreateWithFlags(&ev0, cudaEventDisableTiming);
        cudaEventCreateWithFlags(&evSK, cudaEventDisableTiming);
        cudaEventCreateWithFlags(&evSV, cudaEventDisableTiming);
        cudaEventCreateWithFlags(&evW, cudaEventDisableTiming);
        cudaFuncSetAttribute(gemm_mma<1,1>, cudaFuncAttributeMaxDynamicSharedMemorySize, GSMEM);
        cudaFuncSetAttribute(gemm_mma<1,2>, cudaFuncAttributeMaxDynamicSharedMemorySize, GSMEM);
        cudaFuncSetAttribute(gemm_mma<0,2>, cudaFuncAttributeMaxDynamicSharedMemorySize, GSMEM);
        cudaFuncSetAttribute(gemm_mma<0,0>, cudaFuncAttributeMaxDynamicSharedMemorySize, GSMEM);
        cudaFuncSetAttribute(kv_kernel,  cudaFuncAttributeMaxDynamicSharedMemorySize, KVS_SMEM);
        cudaFuncSetAttribute(attn_kernel, cudaFuncAttributeMaxDynamicSharedMemorySize, AT_SMEM);
        inited = true;
    }

    const int n4x = (int)((size_t)MT * ED / 4);
    const int n4w = ED * ED / 4;
    dim3 blk(256);
    dim3 gblk(512);
    dim3 gsx((n4x + 255) / 256);
    dim3 gsw((n4w + 255) / 256);
    dim3 gg(ED / 256, MT / 128);

    // fork
    cudaEventRecord(ev0, 0);
    cudaStreamWaitEvent(s1, ev0, 0);
    cudaStreamWaitEvent(s2, ev0, 0);
    cudaStreamWaitEvent(s3, ev0, 0);

    // s3: weight converts + zero (fast)
    wconv_kernel<<<gsw, blk, 0, s3>>>(Wq, wq16, n4w);
    wconv_kernel<<<gsw, blk, 0, s3>>>(Wk, wk16, n4w);
    wconv_kernel<<<gsw, blk, 0, s3>>>(Wv, wv16, n4w);
    wconv_kernel<<<gsw, blk, 0, s3>>>(Wo, wo16, n4w);
    zero_small<<<(NB * NH * DH * DH + 255) / 256, 256, 0, s3>>>();
    cudaEventRecord(evW, s3);

    // s1/s2: split K/V (DRAM-bound; overlap gemmQ below)
    split_kernel<<<gsx, blk, 0, s1>>>(k_in, xkh, xkl, n4x);
    cudaEventRecord(evSK, s1);
    split_kernel<<<gsx, blk, 0, s2>>>(v_in, xvh, xvl, n4x);
    cudaEventRecord(evSV, s2);

    // main: split Q first, then gemmQ (splits K/V hide under it)
    split_kernel<<<gsx, blk>>>(q_in, xqh, xql, n4x);
    cudaStreamWaitEvent(0, evW, 0);
    gemm_mma<1,1><<<gg, gblk, GSMEM>>>(xqh, xql, wq16, bq, nullptr, qh, ql);

    // main: gemmK, gemmV (transposed fp16 out)
    cudaStreamWaitEvent(0, evSK, 0);
    gemm_mma<1,2><<<gg, gblk, GSMEM>>>(xkh, xkl, wk16, bk, nullptr, kth, ktl);
    cudaStreamWaitEvent(0, evSV, 0);
    gemm_mma<0,2><<<gg, gblk, GSMEM>>>(xvh, xvl, wv16, bv, nullptr, vth, vtl);

    // main: tensorized kv + finalize + attn + output GEMM
    kv_kernel<<<dim3(8, NH, NB), blk, KVS_SMEM>>>();
    kv_finalize<<<NB * NH, blk>>>();
    attn_kernel<<<dim3(SL / 128, NH, NB), blk, AT_SMEM>>>();
    gemm_mma<0,0><<<gg, gblk, GSMEM>>>(aoh, aol, wo16, bo, out, nullptr, nullptr);
}

// round 10
// speedup vs baseline: 1.3081x; 1.3081x over previous
#include <cuda_runtime.h>
#include <cuda_fp16.h>
#include <math.h>
#include <stdint.h>

#define NB 8
#define SL 8192
#define ED 512
#define NH 8
#define DH 64
#define MT (NB*SL)

// ---------------- scratch (device globals; no allocation) -------------------
__device__ float g_k[(size_t)MT * ED];    // K projection (feature-mapped), fp32
__device__ float g_v[(size_t)MT * ED];    // V projection, fp32
__device__ float g_kv[NB * NH * DH * DH];
__device__ float g_ksum[NB * NH * DH];
// fp16 single input converts
__device__ __half g_xq16[(size_t)MT * ED];
__device__ __half g_xk16[(size_t)MT * ED];
__device__ __half g_xv16[(size_t)MT * ED];
// Q projection (feature-mapped) fp16 hi/lo
__device__ __half g_qh[(size_t)MT * ED];
__device__ __half g_ql[(size_t)MT * ED];
// attn output (fp16 single)
__device__ __half g_ao[(size_t)MT * ED];
// fp16 weights
__device__ __half g_w16[4][ED * ED];
// augmented KV blob (80 rows x 64 cols, swizzled)
__device__ __half g_kvah[NB * NH * 80 * 64];
__device__ __half g_kval[NB * NH * 80 * 64];

// ---------------- helpers ---------------------------------------------------
__device__ __forceinline__ uint32_t smem_u32(const void* p) {
    uint32_t a;
    asm("{ .reg .u64 t; cvta.to.shared.u64 t, %1; cvt.u32.u64 %0, t; }" : "=r"(a) : "l"(p));
    return a;
}
__device__ __forceinline__ uint32_t pack2h(__half a, __half b) {
    __half2 t(a, b);
    return *reinterpret_cast<uint32_t*>(&t);
}
__device__ __forceinline__ void cp16(uint32_t s, const void* g) {
    asm volatile("cp.async.cg.shared.global [%0], [%1], 16;" :: "r"(s), "l"(g));
}
#define CP_COMMIT() asm volatile("cp.async.commit_group;" ::: "memory")
#define CP_WAIT(N)  asm volatile("cp.async.wait_group %0;" :: "n"(N) : "memory")

#define LDSM4(r, addr)                                                         \
    asm volatile("ldmatrix.sync.aligned.m8n8.x4.shared.b16 {%0,%1,%2,%3}, [%4];" \
        : "=r"((r)[0]), "=r"((r)[1]), "=r"((r)[2]), "=r"((r)[3]) : "r"(addr))

#define MMA16816(d, a, b0, b1)                                                 \
    asm volatile("mma.sync.aligned.m16n8k16.row.col.f32.f16.f16.f32 "          \
        "{%0,%1,%2,%3}, {%4,%5,%6,%7}, {%8,%9}, {%0,%1,%2,%3};"                \
        : "+f"((d)[0]), "+f"((d)[1]), "+f"((d)[2]), "+f"((d)[3])               \
        : "r"((a)[0]), "r"((a)[1]), "r"((a)[2]), "r"((a)[3]), "r"(b0), "r"(b1))

// ---------------- fp32 -> fp16 convert ----------------------------------------
__global__ __launch_bounds__(256) void conv_kernel(const float* __restrict__ src,
                                                   __half* __restrict__ dst, int n4)
{
    int i = blockIdx.x * blockDim.x + threadIdx.x;
    if (i >= n4) return;
    float4 v = ((const float4*)src)[i];
    uint2 p;
    p.x = pack2h(__float2half_rn(v.x), __float2half_rn(v.y));
    p.y = pack2h(__float2half_rn(v.z), __float2half_rn(v.w));
    ((uint2*)dst)[i] = p;
}

// ---------------- fp16 1-term GEMM: 512 thr, 128x256 tile, 3-stage -----------
// OMODE: 0 = fp32 C, 1 = fp16 hi/lo
#define A_OFF    0
#define B_OFF    16384
#define STAGE_SZ 49152
#define GSMEM    (3 * STAGE_SZ)

__device__ __forceinline__ void issue_loads(uint32_t st,
                                            const __half* __restrict__ A16,
                                            const __half* __restrict__ Bh,
                                            int bm, int bn, int ch, int tid)
{
    const int kc = ch * 64;
#pragma unroll
    for (int i = 0; i < 2; i++) {
        const int idx = tid + i * 512;
        const int row = idx >> 3;
        const int c = idx & 7;
        cp16(st + A_OFF + row * 128 + ((c ^ (row & 7)) << 4),
             A16 + (size_t)(bm + row) * ED + kc + c * 8);
    }
#pragma unroll
    for (int i = 0; i < 4; i++) {
        const int idx = tid + i * 512;
        const int row = idx >> 3;
        const int c = idx & 7;
        cp16(st + B_OFF + row * 128 + ((c ^ (row & 7)) << 4),
             Bh + (size_t)(bn + row) * ED + kc + c * 8);
    }
    CP_COMMIT();
}

template <int FEAT, int OMODE>
__global__ __launch_bounds__(512, 1) void gemm_mma(const __half* __restrict__ A16,
                                                   const __half* __restrict__ Bh,
                                                   const float* __restrict__ bias,
                                                   float* __restrict__ C,
                                                   __half* __restrict__ Ch,
                                                   __half* __restrict__ Cl)
{
    extern __shared__ char smem_raw[];
    const uint32_t sb = smem_u32(smem_raw);

    const int tid = threadIdx.x;
    const int lane = tid & 31;
    const int wid = tid >> 5;
    const int wm = wid >> 2;
    const int wn = wid & 3;
    const int bm = blockIdx.y * 128;
    const int bn = blockIdx.x * 256;

    float acc[2][8][4];
#pragma unroll
    for (int i = 0; i < 2; i++)
#pragma unroll
        for (int j = 0; j < 8; j++)
#pragma unroll
            for (int q = 0; q < 4; q++) acc[i][j][q] = 0.f;

    issue_loads(sb, A16, Bh, bm, bn, 0, tid);
    issue_loads(sb + STAGE_SZ, A16, Bh, bm, bn, 1, tid);

#pragma unroll 1
    for (int ch = 0; ch < 8; ch++) {
        if (ch < 6) {
            issue_loads(sb + ((ch + 2) % 3) * STAGE_SZ, A16, Bh, bm, bn, ch + 2, tid);
            CP_WAIT(2);
        } else if (ch == 6) {
            CP_WAIT(1);
        } else {
            CP_WAIT(0);
        }
        __syncthreads();

        const uint32_t cur = sb + (ch % 3) * STAGE_SZ;
        const uint32_t sA = cur + A_OFF;
        const uint32_t sB = cur + B_OFF;

        uint32_t fa[2][2][4];   // [buf][mf][4]
        uint32_t fb[2][4];

        #define LOAD_A(s16, buf)                                               \
        {                                                                      \
            _Pragma("unroll")                                                  \
            for (int mf = 0; mf < 2; mf++) {                                   \
                const int arow = wm * 32 + mf * 16 + (lane & 15);              \
                const int achk = (s16) * 2 + (lane >> 4);                      \
                LDSM4(fa[buf][mf], sA + arow * 128 + ((achk ^ (arow & 7)) << 4)); \
            }                                                                  \
        }
        #define LOAD_B(s16, nf, buf)                                           \
        {                                                                       \
            const int brow = wn * 64 + (nf) * 16 + (lane & 7) + ((lane >> 4) << 3); \
            const int bchk = (s16) * 2 + ((lane >> 3) & 1);                    \
            LDSM4(fb[buf], sB + brow * 128 + ((bchk ^ (brow & 7)) << 4));      \
        }

        LOAD_A(0, 0);
        LOAD_B(0, 0, 0);

#pragma unroll
        for (int s16 = 0; s16 < 4; s16++) {
            const int ab = s16 & 1;
#pragma unroll
            for (int nf = 0; nf < 4; nf++) {
                const int bb = nf & 1;
                if (nf < 3) {
                    LOAD_B(s16, nf + 1, bb ^ 1);
                } else if (s16 < 3) {
                    LOAD_A(s16 + 1, ab ^ 1);
                    LOAD_B(s16 + 1, 0, bb ^ 1);
                }
#pragma unroll
                for (int mf = 0; mf < 2; mf++) {
                    MMA16816(acc[mf][2 * nf],     fa[ab][mf], fb[bb][0], fb[bb][1]);
                    MMA16816(acc[mf][2 * nf + 1], fa[ab][mf], fb[bb][2], fb[bb][3]);
                }
            }
        }
        #undef LOAD_A
        #undef LOAD_B
        __syncthreads();
    }

    // Epilogue
#pragma unroll
    for (int mf = 0; mf < 2; mf++) {
        const int row0 = bm + wm * 32 + mf * 16 + (lane >> 2);
#pragma unroll
        for (int nf8 = 0; nf8 < 8; nf8++) {
            const int col = bn + wn * 64 + nf8 * 8 + (lane & 3) * 2;
            const float b0 = bias[col], b1 = bias[col + 1];
            float x0 = acc[mf][nf8][0] + b0;
            float x1 = acc[mf][nf8][1] + b1;
            float x2 = acc[mf][nf8][2] + b0;
            float x3 = acc[mf][nf8][3] + b1;
            if (FEAT) {
                x0 = (x0 > 0.f) ? (x0 + 1.f) : expf(x0);
                x1 = (x1 > 0.f) ? (x1 + 1.f) : expf(x1);
                x2 = (x2 > 0.f) ? (x2 + 1.f) : expf(x2);
                x3 = (x3 > 0.f) ? (x3 + 1.f) : expf(x3);
            }
            if (OMODE == 0) {
                *(float2*)&C[(size_t)row0 * ED + col]       = make_float2(x0, x1);
                *(float2*)&C[(size_t)(row0 + 8) * ED + col] = make_float2(x2, x3);
            } else {
                __half h0 = __float2half_rn(x0), h1 = __float2half_rn(x1);
                __half h2 = __float2half_rn(x2), h3 = __float2half_rn(x3);
                __half e0 = __float2half_rn(x0 - __half2float(h0));
                __half e1 = __float2half_rn(x1 - __half2float(h1));
                __half e2 = __float2half_rn(x2 - __half2float(h2));
                __half e3 = __float2half_rn(x3 - __half2float(h3));
                *(uint32_t*)&Ch[(size_t)row0 * ED + col]       = pack2h(h0, h1);
                *(uint32_t*)&Cl[(size_t)row0 * ED + col]       = pack2h(e0, e1);
                *(uint32_t*)&Ch[(size_t)(row0 + 8) * ED + col] = pack2h(h2, h3);
                *(uint32_t*)&Cl[(size_t)(row0 + 8) * ED + col] = pack2h(e2, e3);
            }
        }
    }
}

// ---------------- zeroing ----------------------------------------------------
__global__ void zero_small()
{
    int i = blockIdx.x * blockDim.x + threadIdx.x;
    if (i < NB * NH * DH * DH) g_kv[i] = 0.f;
    if (i < NB * NH * DH)      g_ksum[i] = 0.f;
}

// ---------------- KV (proven fp32 version) -----------------------------------
__global__ __launch_bounds__(256) void kv_kernel()
{
    __shared__ float Ksh[32][64];
    __shared__ float Vsh[32][64];

    const int tid = threadIdx.x;
    const int sp = blockIdx.x;
    const int h = blockIdx.y;
    const int n = blockIdx.z;
    const int tx = tid & 15;
    const int ty = tid >> 4;
    const int s0 = sp * (SL / 8);

    float acc[4][4];
#pragma unroll
    for (int i = 0; i < 4; i++)
#pragma unroll
        for (int j = 0; j < 4; j++) acc[i][j] = 0.f;
    float ks = 0.f;

    for (int st = 0; st < SL / 8; st += 32) {
        __syncthreads();
#pragma unroll
        for (int t = tid; t < 512; t += 256) {
            const int r = t >> 4;
            const int c = (t & 15) * 4;
            const size_t g = ((size_t)(n * SL + s0 + st + r)) * ED + h * DH + c;
            *(float4*)&Ksh[r][c] = *(const float4*)&g_k[g];
            *(float4*)&Vsh[r][c] = *(const float4*)&g_v[g];
        }
        __syncthreads();
#pragma unroll 8
        for (int ss = 0; ss < 32; ss++) {
            float4 vm = *(const float4*)&Vsh[ss][ty * 4];
            float4 kd = *(const float4*)&Ksh[ss][tx * 4];
            const float a[4] = {vm.x, vm.y, vm.z, vm.w};
            const float b[4] = {kd.x, kd.y, kd.z, kd.w};
#pragma unroll
            for (int i = 0; i < 4; i++)
#pragma unroll
                for (int j = 0; j < 4; j++)
                    acc[i][j] = fmaf(a[i], b[j], acc[i][j]);
        }
        if (tid < 64) {
#pragma unroll 8
            for (int ss = 0; ss < 32; ss++) ks += Ksh[ss][tid];
        }
    }

    const int bse = (n * NH + h) * DH * DH;
#pragma unroll
    for (int i = 0; i < 4; i++)
#pragma unroll
        for (int j = 0; j < 4; j++)
            atomicAdd(&g_kv[bse + (ty * 4 + i) * DH + tx * 4 + j], acc[i][j]);
    if (tid < 64)
        atomicAdd(&g_ksum[(n * NH + h) * DH + tid], ks);
}

// ---------------- KV finalize: fp32 -> augmented fp16 hi/lo (swizzled) -------
__global__ __launch_bounds__(256) void kv_finalize()
{
    const int nh = blockIdx.x;
    const float* kv = g_kv + nh * 4096;
    const float* ks = g_ksum + nh * 64;
    char* oh = (char*)g_kvah + (size_t)nh * 10240;
    char* ol = (char*)g_kval + (size_t)nh * 10240;
    for (int idx = threadIdx.x; idx < 80 * 64; idx += 256) {
        const int r = idx >> 6, d = idx & 63;
        float x = (r < 64) ? kv[r * 64 + d] : (r == 64 ? ks[d] : 0.f);
        __half hh = __float2half_rn(x);
        __half ll = __float2half_rn(x - __half2float(hh));
        uint32_t off = r * 128 + d * 2;
        uint32_t sw = off ^ ((off >> 3) & 0x70);
        *(__half*)(oh + sw) = hh;
        *(__half*)(ol + sw) = ll;
    }
}

// ---------------- tensorized attn (proven R8/R9), hi-only output -------------
#define AT_QH 0
#define AT_QL 16384
#define AT_BH 32768
#define AT_BL 43008
#define AT_SMEM 53248

__global__ __launch_bounds__(256) void attn_kernel()
{
    extern __shared__ char smem_raw[];
    const uint32_t sb = smem_u32(smem_raw);
    const int tid = threadIdx.x;
    const int lane = tid & 31;
    const int wid = tid >> 5;
    const int l0 = blockIdx.x * 128;
    const int h = blockIdx.y;
    const int n = blockIdx.z;
    const int nh = n * NH + h;

#pragma unroll
    for (int it = 0; it < 8; it++) {
        int idx = tid + it * 256;
        int buf = idx >> 10;
        int r = (idx >> 3) & 127;
        int c = idx & 7;
        uint32_t soff = (buf ? AT_QL : AT_QH) + r * 128 + ((c ^ (r & 7)) << 4);
        const __half* src = buf ? g_ql : g_qh;
        cp16(sb + soff, src + (size_t)(n * SL + l0 + r) * ED + h * DH + c * 8);
    }
#pragma unroll
    for (int it = 0; it < 5; it++) {
        int idx = tid + it * 256;
        int buf = idx >= 640;
        int ch = buf ? idx - 640 : idx;
        cp16(sb + (buf ? AT_BL : AT_BH) + ch * 16,
             (buf ? g_kval : g_kvah) + (size_t)nh * 5120 + ch * 8);
    }
    CP_COMMIT();
    CP_WAIT(0);
    __syncthreads();

    float acc[9][4];
#pragma unroll
    for (int j = 0; j < 9; j++)
#pragma unroll
        for (int q = 0; q < 4; q++) acc[j][q] = 0.f;

#pragma unroll
    for (int kstep = 0; kstep < 4; kstep++) {
        uint32_t fah[4], fal[4];
        {
            const int arow = wid * 16 + (lane & 15);
            const int achk = kstep * 2 + (lane >> 4);
            const uint32_t aoff = arow * 128 + ((achk ^ (arow & 7)) << 4);
            LDSM4(fah, sb + AT_QH + aoff);
            LDSM4(fal, sb + AT_QL + aoff);
        }
        uint32_t fbh[5][4], fbl[5][4];
#pragma unroll
        for (int p = 0; p < 5; p++) {
            const int brow = p * 16 + (lane & 7) + ((lane >> 4) << 3);
            const int bchk = kstep * 2 + ((lane >> 3) & 1);
            const uint32_t boff = brow * 128 + ((bchk ^ (brow & 7)) << 4);
            LDSM4(fbh[p], sb + AT_BH + boff);
            LDSM4(fbl[p], sb + AT_BL + boff);
        }
#pragma unroll
        for (int j = 0; j < 9; j++) {
            uint32_t bh0 = fbh[j >> 1][(j & 1) * 2], bh1 = fbh[j >> 1][(j & 1) * 2 + 1];
            uint32_t bl0 = fbl[j >> 1][(j & 1) * 2], bl1 = fbl[j >> 1][(j & 1) * 2 + 1];
            MMA16816(acc[j], fah, bh0, bh1);
            MMA16816(acc[j], fah, bl0, bl1);
            MMA16816(acc[j], fal, bh0, bh1);
        }
    }

    const float zd0 = __shfl_sync(0xFFFFFFFFu, acc[8][0], lane & ~3);
    const float zd1 = __shfl_sync(0xFFFFFFFFu, acc[8][2], lane & ~3);
    const float z0 = 1.f / (fmaxf(zd0, 0.f) + 1e-6f);
    const float z1 = 1.f / (fmaxf(zd1, 0.f) + 1e-6f);
    const int g = lane >> 2, tig = lane & 3;
    const int row0 = l0 + wid * 16 + g;

#pragma unroll
    for (int j = 0; j < 8; j++) {
        const int e = h * DH + j * 8 + tig * 2;
        float x0 = acc[j][0] * z0, x1 = acc[j][1] * z0;
        float x2 = acc[j][2] * z1, x3 = acc[j][3] * z1;
        *(uint32_t*)&g_ao[(size_t)(n * SL + row0) * ED + e] =
            pack2h(__float2half_rn(x0), __float2half_rn(x1));
        *(uint32_t*)&g_ao[(size_t)(n * SL + row0 + 8) * ED + e] =
            pack2h(__float2half_rn(x2), __float2half_rn(x3));
    }
}

// ---------------- launch -----------------------------------------------------
extern "C" void kernel_launch(void* const* d_in, const int* in_sizes, int n_in,
                              void* d_out, int out_size)
{
    const float* q_in = (const float*)d_in[0];
    const float* k_in = (const float*)d_in[1];
    const float* v_in = (const float*)d_in[2];
    const float* Wq = (const float*)d_in[3];
    const float* bq = (const float*)d_in[4];
    const float* Wk = (const float*)d_in[5];
    const float* bk = (const float*)d_in[6];
    const float* Wv = (const float*)d_in[7];
    const float* bv = (const float*)d_in[8];
    const float* Wo = (const float*)d_in[9];
    const float* bo = (const float*)d_in[10];
    float* out = (float*)d_out;

    float *pk, *pv;
    __half *xq16, *xk16, *xv16, *qh, *ql, *ao, *w16;
    cudaGetSymbolAddress((void**)&pk, g_k);
    cudaGetSymbolAddress((void**)&pv, g_v);
    cudaGetSymbolAddress((void**)&xq16, g_xq16);
    cudaGetSymbolAddress((void**)&xk16, g_xk16);
    cudaGetSymbolAddress((void**)&xv16, g_xv16);
    cudaGetSymbolAddress((void**)&qh, g_qh);
    cudaGetSymbolAddress((void**)&ql, g_ql);
    cudaGetSymbolAddress((void**)&ao, g_ao);
    cudaGetSymbolAddress((void**)&w16, g_w16);
    __half* wq16 = w16;
    __half* wk16 = w16 + (size_t)ED * ED;
    __half* wv16 = w16 + (size_t)2 * ED * ED;
    __half* wo16 = w16 + (size_t)3 * ED * ED;

    static cudaStream_t s1, s2, s3;
    static cudaEvent_t ev0, evSK, evSV, evW;
    static bool inited = false;
    if (!inited) {
        cudaStreamCreateWithFlags(&s1, cudaStreamNonBlocking);
        cudaStreamCreateWithFlags(&s2, cudaStreamNonBlocking);
        cudaStreamCreateWithFlags(&s3, cudaStreamNonBlocking);
        cudaEventCreateWithFlags(&ev0, cudaEventDisableTiming);
        cudaEventCreateWithFlags(&evSK, cudaEventDisableTiming);
        cudaEventCreateWithFlags(&evSV, cudaEventDisableTiming);
        cudaEventCreateWithFlags(&evW, cudaEventDisableTiming);
        cudaFuncSetAttribute(gemm_mma<1,1>, cudaFuncAttributeMaxDynamicSharedMemorySize, GSMEM);
        cudaFuncSetAttribute(gemm_mma<1,0>, cudaFuncAttributeMaxDynamicSharedMemorySize, GSMEM);
        cudaFuncSetAttribute(gemm_mma<0,0>, cudaFuncAttributeMaxDynamicSharedMemorySize, GSMEM);
        cudaFuncSetAttribute(attn_kernel, cudaFuncAttributeMaxDynamicSharedMemorySize, AT_SMEM);
        inited = true;
    }

    const int n4x = (int)((size_t)MT * ED / 4);
    const int n4w = ED * ED / 4;
    dim3 blk(256);
    dim3 gblk(512);
    dim3 gsx((n4x + 255) / 256);
    dim3 gsw((n4w + 255) / 256);
    dim3 gg(ED / 256, MT / 128);

    // fork
    cudaEventRecord(ev0, 0);
    cudaStreamWaitEvent(s1, ev0, 0);
    cudaStreamWaitEvent(s2, ev0, 0);
    cudaStreamWaitEvent(s3, ev0, 0);

    // s3: weight converts + zero
    conv_kernel<<<gsw, blk, 0, s3>>>(Wq, wq16, n4w);
    conv_kernel<<<gsw, blk, 0, s3>>>(Wk, wk16, n4w);
    conv_kernel<<<gsw, blk, 0, s3>>>(Wv, wv16, n4w);
    conv_kernel<<<gsw, blk, 0, s3>>>(Wo, wo16, n4w);
    zero_small<<<(NB * NH * DH * DH + 255) / 256, 256, 0, s3>>>();
    cudaEventRecord(evW, s3);

    // s1/s2: input converts for K/V (hidden under gemmQ)
    conv_kernel<<<gsx, blk, 0, s1>>>(k_in, xk16, n4x);
    cudaEventRecord(evSK, s1);
    conv_kernel<<<gsx, blk, 0, s2>>>(v_in, xv16, n4x);
    cudaEventRecord(evSV, s2);

    // main: convQ, gemmQ (fp16 hi/lo out)
    conv_kernel<<<gsx, blk>>>(q_in, xq16, n4x);
    cudaStreamWaitEvent(0, evW, 0);
    gemm_mma<1,1><<<gg, gblk, GSMEM>>>(xq16, wq16, bq, nullptr, qh, ql);

    // main: gemmK, gemmV (fp32 out)
    cudaStreamWaitEvent(0, evSK, 0);
    gemm_mma<1,0><<<gg, gblk, GSMEM>>>(xk16, wk16, bk, pk, nullptr, nullptr);
    cudaStreamWaitEvent(0, evSV, 0);
    gemm_mma<0,0><<<gg, gblk, GSMEM>>>(xv16, wv16, bv, pv, nullptr, nullptr);

    // main: kv + finalize + attn + output GEMM
    kv_kernel<<<dim3(8, NH, NB), blk>>>();
    kv_finalize<<<NB * NH, blk>>>();
    attn_kernel<<<dim3(SL / 128, NH, NB), blk, AT_SMEM>>>();
    gemm_mma<0,0><<<gg, gblk, GSMEM>>>(ao, wo16, bo, out, nullptr, nullptr);
}